// round 1
// baseline (speedup 1.0000x reference)
#include <cuda_runtime.h>
#include <math.h>

#define B 32
#define S 512
#define H 256
#define T 48
#define START_IDX 46
#define STOP_IDX 47

// Scratch (no allocations allowed): exp(emission) and emission-at-gold-tag
__device__ float g_expEm[B * S * T];    // 3 MB
__device__ float g_emAtTag[B * S];      // 64 KB

// ---------------------------------------------------------------------------
// Kernel A: emission = feat @ W + bias; store exp(emission) and em[b,s,tags[b,s]]
// Grid: 128 blocks x 256 threads. Each block: 128 rows x 48 cols, K=256.
// Thread tile: 4 rows x 6 cols.
// ---------------------------------------------------------------------------
__global__ __launch_bounds__(256) void emis_kernel(
    const float* __restrict__ feat,   // [B*S, H]
    const float* __restrict__ Wm,     // [H, T]
    const float* __restrict__ bias,   // [T]
    const int*   __restrict__ tags)   // [B*S]
{
    const int P = 129;                       // smem pitch (conflict break)
    __shared__ float sh_W[64 * T];           // 12 KB
    __shared__ float sh_feat[64 * P];        // 33 KB  (transposed: [k][row])

    const int tid  = threadIdx.x;
    const int row0 = blockIdx.x * 128;
    const int rg   = tid >> 3;   // 0..31 -> rows rg*4..rg*4+3
    const int cg   = tid & 7;    // 0..7  -> cols cg*6..cg*6+5

    float acc[4][6];
#pragma unroll
    for (int r = 0; r < 4; r++)
#pragma unroll
        for (int c = 0; c < 6; c++) acc[r][c] = 0.0f;

    for (int kc = 0; kc < H; kc += 64) {
        // load W chunk [64][48], contiguous
        for (int u = tid; u < 64 * T; u += 256) sh_W[u] = Wm[kc * T + u];

        // load feat chunk transposed into sh_feat[k][row]
#pragma unroll
        for (int m = 0; m < 8; m++) {
            int u   = tid + m * 256;      // 0..2047
            int row = u >> 4;             // 0..127
            int k4  = u & 15;             // 0..15 (float4 index)
            float4 v = reinterpret_cast<const float4*>(feat)
                        [(size_t)(row0 + row) * (H / 4) + (kc >> 2) + k4];
            sh_feat[(k4 * 4 + 0) * P + row] = v.x;
            sh_feat[(k4 * 4 + 1) * P + row] = v.y;
            sh_feat[(k4 * 4 + 2) * P + row] = v.z;
            sh_feat[(k4 * 4 + 3) * P + row] = v.w;
        }
        __syncthreads();

#pragma unroll 16
        for (int k = 0; k < 64; k++) {
            float f0 = sh_feat[k * P + rg * 4 + 0];
            float f1 = sh_feat[k * P + rg * 4 + 1];
            float f2 = sh_feat[k * P + rg * 4 + 2];
            float f3 = sh_feat[k * P + rg * 4 + 3];
            float2 w01 = *reinterpret_cast<const float2*>(&sh_W[k * T + cg * 6 + 0]);
            float2 w23 = *reinterpret_cast<const float2*>(&sh_W[k * T + cg * 6 + 2]);
            float2 w45 = *reinterpret_cast<const float2*>(&sh_W[k * T + cg * 6 + 4]);
            float w[6] = {w01.x, w01.y, w23.x, w23.y, w45.x, w45.y};
            float f[4] = {f0, f1, f2, f3};
#pragma unroll
            for (int r = 0; r < 4; r++)
#pragma unroll
                for (int c = 0; c < 6; c++)
                    acc[r][c] = fmaf(f[r], w[c], acc[r][c]);
        }
        __syncthreads();
    }

    // epilogue: bias, exp, store; capture emission at gold tag
#pragma unroll
    for (int rr = 0; rr < 4; rr++) {
        int row = row0 + rg * 4 + rr;
        int tag = __ldg(&tags[row]);
#pragma unroll
        for (int cc = 0; cc < 6; cc++) {
            int c = cg * 6 + cc;
            float em = acc[rr][cc] + __ldg(&bias[c]);
            g_expEm[(size_t)row * T + c] = expf(em);
            if (c == tag) g_emAtTag[row] = em;
        }
    }
}

// ---------------------------------------------------------------------------
// Kernel B: forward recursion in scaled-linear space + terminal LSE + gold.
// Grid: B blocks x 64 threads (thread j owns tag column j; j>=48 padded).
// a[j] = exp(alpha[j] - C); step: a'[j] = expEm[j] * dot(a, expT[:,j]).
// Rescale by block max every 4 steps.
// ---------------------------------------------------------------------------
__global__ __launch_bounds__(64) void fwd_kernel(
    const float* __restrict__ trans,     // [T,T]
    const int*   __restrict__ lengths,   // [B]
    const int*   __restrict__ tags,      // [B,S]
    float*       __restrict__ out)       // [B]
{
    __shared__ float sh_trans[T * T];
    __shared__ __align__(16) float a_sh[2][64];
    __shared__ float red[2];

    const int tid  = threadIdx.x;
    const int b    = blockIdx.x;
    const int lane = tid & 31;
    const int wid  = tid >> 5;
    const int j    = tid;

    for (int u = tid; u < T * T; u += 64) sh_trans[u] = trans[u];
    __syncthreads();

    // per-thread transition column in registers (linear space)
    float eT[T];
#pragma unroll
    for (int i = 0; i < T; i++) eT[i] = 0.0f;
    float eStop = 0.0f;
    if (j < T) {
#pragma unroll
        for (int i = 0; i < T; i++) eT[i] = expf(sh_trans[i * T + j]);
        eStop = expf(sh_trans[j * T + STOP_IDX]);   // exp(trans[j][STOP])
    }

    a_sh[0][tid] = (tid == START_IDX) ? 1.0f : 0.0f;
    __syncthreads();

    const int len = lengths[b];
    const float* pe = g_expEm + (size_t)b * S * T + j;

    float C   = 0.0f;
    int   buf = 0;
    float e   = (j < T) ? pe[0] : 0.0f;   // prefetched expEm for s=0

    for (int s = 0; s < len; s++) {
        const float4* av = reinterpret_cast<const float4*>(a_sh[buf]);
        float d0 = 0.f, d1 = 0.f, d2 = 0.f, d3 = 0.f;
#pragma unroll
        for (int q = 0; q < T / 4; q++) {
            float4 a4 = av[q];
            d0 = fmaf(a4.x, eT[4 * q + 0], d0);
            d1 = fmaf(a4.y, eT[4 * q + 1], d1);
            d2 = fmaf(a4.z, eT[4 * q + 2], d2);
            d3 = fmaf(a4.w, eT[4 * q + 3], d3);
        }
        float val = (j < T) ? e * ((d0 + d1) + (d2 + d3)) : 0.0f;

        // prefetch next step's expEm
        if (j < T && s + 1 < len) e = pe[(size_t)(s + 1) * T];

        const int nbuf = buf ^ 1;
        a_sh[nbuf][tid] = val;

        const bool resc = ((s & 3) == 3);
        if (resc) {
            float m = val;
#pragma unroll
            for (int o = 16; o; o >>= 1)
                m = fmaxf(m, __shfl_xor_sync(0xffffffffu, m, o));
            if (lane == 0) red[wid] = m;
        }
        __syncthreads();
        if (resc) {
            float M   = fmaxf(red[0], red[1]);
            float inv = 1.0f / M;
            a_sh[nbuf][tid] = val * inv;
            C += logf(M);
            __syncthreads();
        }
        buf = nbuf;
    }

    // terminal: logZ = C + log( sum_j a[j] * exp(trans[j][STOP]) )
    float tj = (j < T) ? a_sh[buf][j] * eStop : 0.0f;
#pragma unroll
    for (int o = 16; o; o >>= 1) tj += __shfl_xor_sync(0xffffffffu, tj, o);
    if (lane == 0) red[wid] = tj;
    __syncthreads();
    const float logZ = C + logf(red[0] + red[1]);
    __syncthreads();   // before reusing red[]

    // gold score
    const int* btags = tags + b * S;
    float g = 0.0f;
    for (int s = tid; s < len; s += 64) {
        int to   = btags[s];
        int from = (s == 0) ? START_IDX : btags[s - 1];
        g += sh_trans[from * T + to] + g_emAtTag[(size_t)b * S + s];
    }
#pragma unroll
    for (int o = 16; o; o >>= 1) g += __shfl_xor_sync(0xffffffffu, g, o);
    if (lane == 0) red[wid] = g;
    __syncthreads();

    if (tid == 0) {
        float gold = red[0] + red[1] + sh_trans[btags[len - 1] * T + STOP_IDX];
        out[b] = logZ - gold;
    }
}

// ---------------------------------------------------------------------------
extern "C" void kernel_launch(void* const* d_in, const int* in_sizes, int n_in,
                              void* d_out, int out_size)
{
    const float* feat    = (const float*)d_in[0];  // lstm_features [B,S,H]
    const float* Wm      = (const float*)d_in[1];  // emission_w [H,T]
    const float* bias    = (const float*)d_in[2];  // emission_b [T]
    const float* trans   = (const float*)d_in[3];  // transitions [T,T]
    const int*   lengths = (const int*)d_in[4];    // [B]
    const int*   tags    = (const int*)d_in[5];    // [B,S]
    float*       out     = (float*)d_out;          // [B]

    emis_kernel<<<(B * S) / 128, 256>>>(feat, Wm, bias, tags);
    fwd_kernel<<<B, 64>>>(trans, lengths, tags, out);
}